// round 10
// baseline (speedup 1.0000x reference)
#include <cuda_runtime.h>
#include <cuda_fp16.h>
#include <math.h>
#include <stdint.h>

// ---------------- problem constants ----------------
#define B_TOTAL   131072
#define DH        32
#define TWO_PI_F  6.283185307179586f

// ---------------- device scratch (static, no alloc) ----------------
__device__ __half g_xhi[(size_t)B_TOTAL * 64];
__device__ __half g_xlo[(size_t)B_TOTAL * 64];
__device__ __half g_hhi[(size_t)B_TOTAL * 512];
__device__ __half g_hlo[(size_t)B_TOTAL * 512];
__device__ __half g_w1hi[512 * 64];    // W1^T [n=512][k=64]
__device__ __half g_w1lo[512 * 64];
__device__ __half g_w2hi[512 * 512];   // (W2*eta)^T [n=512][k=512]
__device__ __half g_w2lo[512 * 512];

__device__ __forceinline__ void split_h(float v, __half& hi, __half& lo) {
    hi = __float2half_rn(v);
    lo = __float2half_rn(v - __half2float(hi));
}

// ---------------- pack kernels ----------------
__global__ void pack_x_kernel(const float* __restrict__ x) {
    size_t i = (size_t)blockIdx.x * blockDim.x + threadIdx.x;  // B*64
    __half hi, lo;
    split_h(x[i], hi, lo);
    g_xhi[i] = hi;
    g_xlo[i] = lo;
}
__global__ void pack_w1_kernel(const float* __restrict__ W1) {
    int i = blockIdx.x * blockDim.x + threadIdx.x;   // 512*64
    int n = i >> 6, k = i & 63;
    __half hi, lo;
    split_h(W1[k * 512 + n], hi, lo);
    g_w1hi[i] = hi;    // [n][k] layout, i = n*64+k
    g_w1lo[i] = lo;
}
__global__ void pack_w2_kernel(const float* __restrict__ W2,
                               const float* __restrict__ eta) {
    int i = blockIdx.x * blockDim.x + threadIdx.x;   // 512*512
    int n = i >> 9, k = i & 511;
    __half hi, lo;
    split_h(W2[k * 513 + n] * eta[0], hi, lo);
    g_w2hi[i] = hi;    // [n][k], i = n*512+k
    g_w2lo[i] = lo;
}

// ---------------------------------------------------------------------------
// fp16x3-split GEMM via mma.sync m16n8k16, fused hi/lo chunks.
// CTA: 256 threads (8 warps), 2 CTAs/SM. Tile M=128 x N=128;
// warp grid 4(m) x 2(n), warp tile 32x64 -> acc[2][8][4] fp32.
// Chunk = k32 slice: smem rows are 128B = [hi 64B | lo 64B] for both A and B
// (A 16KB + B 16KB = 32KB). Per k16 step: load a_hi,b_hi,a_lo,b_lo fragments,
// issue 3 MMA sets (a_hi*b_hi, a_lo*b_hi, a_hi*b_lo) into one accumulator
// -> 0.25 ldmatrix.x4 per HMMA (was 0.375) and -33% global traffic.
// 3-stage cp.async pipeline (96KB/CTA), 16B-XOR swizzle.
// Grid: (4 n-quarters, B/128 row-tiles), x fastest (A/h reads L2-hot).
// PHASE1: A=x splits, B=W1^T splits, epilogue relu+split -> g_h{hi,lo}
// PHASE2: A=h splits, B=(W2*eta)^T splits, epilogue Moebius -> out
// ---------------------------------------------------------------------------
template <int KSEG, bool PHASE1>
__global__ __launch_bounds__(256, 2)
void mma_gemm_kernel(const float* __restrict__ bias,
                     const float* __restrict__ theta,
                     const float* __restrict__ r_in,
                     const float* __restrict__ eta,
                     float* __restrict__ out) {
    constexpr int NC = KSEG / 32;       // k32 chunks
    constexpr int SSTRIDE = KSEG * 2;   // source row stride (bytes)
    constexpr int STAGES = 3;
    constexpr int CHUNK_BYTES = 32768;  // A 16KB + B 16KB

    extern __shared__ char smem[];
    const uint32_t sbase = (uint32_t)__cvta_generic_to_shared(smem);

    const int tid = threadIdx.x;
    const int lane = tid & 31;
    const int wid = tid >> 5;
    const int wm = (wid & 3) * 32;       // warp M offset within CTA tile
    const int wn = (wid >> 2) * 64;      // warp N offset within CTA tile
    const int blockRow = blockIdx.y * 128;
    const int colbase = blockIdx.x * 128;

    const __half* Ahi = PHASE1 ? g_xhi : g_hhi;
    const __half* Alo = PHASE1 ? g_xlo : g_hlo;
    const __half* Bhi = PHASE1 ? g_w1hi : g_w2hi;
    const __half* Blo = PHASE1 ? g_w1lo : g_w2lo;

    float acc[2][8][4];
#pragma unroll
    for (int mi = 0; mi < 2; mi++)
#pragma unroll
        for (int nj = 0; nj < 8; nj++)
#pragma unroll
            for (int q = 0; q < 4; q++) acc[mi][nj][q] = 0.0f;

    // ldmatrix lane-address components.
    // A (m16 x k16 per x4): lane bit3 -> +8 rows, bit4 -> +8 k-halves.
    const int aRow = wm + (lane & 7) + ((lane >> 3) & 1) * 8;
    const int aU = (lane >> 4) & 1;
    const int aX = aRow & 7;
    // B (two n8 x k16 per x4): bit4 -> +8 n-rows, bit3 -> +8 k-halves.
    const int bRow = wn + (lane & 7) + ((lane >> 4) & 1) * 8;
    const int bU = (lane >> 3) & 1;
    const int bX = bRow & 7;

    // chunk kc covers k-columns [kc*32, kc*32+32); smem row = [hi 64B | lo 64B]
    auto loadc = [&](int kc) {
        const char* ah = (const char*)Ahi + (size_t)blockRow * SSTRIDE + (size_t)kc * 64;
        const char* al = (const char*)Alo + (size_t)blockRow * SSTRIDE + (size_t)kc * 64;
        const char* bh = (const char*)Bhi + (size_t)colbase * SSTRIDE + (size_t)kc * 64;
        const char* bl = (const char*)Blo + (size_t)colbase * SSTRIDE + (size_t)kc * 64;
        uint32_t ab = sbase + (uint32_t)(kc % STAGES) * CHUNK_BYTES;
        uint32_t bb = ab + 16384u;
#pragma unroll
        for (int j = 0; j < 4; j++) {                 // A: 1024 x 16B units
            int gi = tid + 256 * j;
            int row = gi >> 3, u = gi & 7;
            const char* base = (u < 4) ? ah : al;
            const char* src = base + (size_t)row * SSTRIDE + (u & 3) * 16;
            uint32_t dst = ab + row * 128u + (uint32_t)((u ^ (row & 7)) << 4);
            asm volatile("cp.async.cg.shared.global [%0], [%1], 16;"
                         :: "r"(dst), "l"(src));
        }
#pragma unroll
        for (int j = 0; j < 4; j++) {                 // B: 1024 x 16B units
            int gi = tid + 256 * j;
            int row = gi >> 3, u = gi & 7;
            const char* base = (u < 4) ? bh : bl;
            const char* src = base + (size_t)row * SSTRIDE + (u & 3) * 16;
            uint32_t dst = bb + row * 128u + (uint32_t)((u ^ (row & 7)) << 4);
            asm volatile("cp.async.cg.shared.global [%0], [%1], 16;"
                         :: "r"(dst), "l"(src));
        }
        asm volatile("cp.async.commit_group;");
    };

#define LDSM_X4(r0, r1, r2, r3, addr)                                        \
    asm volatile(                                                            \
        "ldmatrix.sync.aligned.m8n8.x4.shared.b16 {%0,%1,%2,%3}, [%4];"      \
        : "=r"(r0), "=r"(r1), "=r"(r2), "=r"(r3) : "r"(addr))

#define MMA16816(d, a, b)                                                    \
    asm volatile(                                                            \
        "mma.sync.aligned.m16n8k16.row.col.f32.f16.f16.f32 "                 \
        "{%0,%1,%2,%3}, {%4,%5,%6,%7}, {%8,%9}, {%0,%1,%2,%3};"              \
        : "+f"((d)[0]), "+f"((d)[1]), "+f"((d)[2]), "+f"((d)[3])             \
        : "r"((a)[0]), "r"((a)[1]), "r"((a)[2]), "r"((a)[3]),                \
          "r"((b)[0]), "r"((b)[1]))

    // ---- prologue: fill STAGES-1 buffers ----
#pragma unroll
    for (int s = 0; s < STAGES - 1; s++) {
        if (s < NC) loadc(s);
        else asm volatile("cp.async.commit_group;");
    }
    asm volatile("cp.async.wait_group %0;" :: "n"(STAGES - 2));
    __syncthreads();   // chunk 0 visible

#pragma unroll 1
    for (int c = 0; c < NC; c++) {
        if (c + STAGES - 1 < NC) loadc(c + STAGES - 1);
        else asm volatile("cp.async.commit_group;");

        uint32_t ab = sbase + (uint32_t)(c % STAGES) * CHUNK_BYTES;
        uint32_t bb = ab + 16384u;
#pragma unroll
        for (int kk = 0; kk < 2; kk++) {
            // hi units 0..3 hold k[0,32), lo units 4..7 hold the lo split
            uint32_t a_hi[2][4], a_lo[2][4];
#pragma unroll
            for (int mi = 0; mi < 2; mi++) {
                int row = aRow + mi * 16;
                uint32_t addr_h = ab + row * 128u +
                                  (uint32_t)(((kk * 2 + aU) ^ aX) << 4);
                LDSM_X4(a_hi[mi][0], a_hi[mi][1], a_hi[mi][2], a_hi[mi][3], addr_h);
            }
            uint32_t b_hi[8][2], b_lo[8][2];
#pragma unroll
            for (int p = 0; p < 4; p++) {
                int row = bRow + p * 16;
                uint32_t addr_h = bb + row * 128u +
                                  (uint32_t)(((kk * 2 + bU) ^ bX) << 4);
                LDSM_X4(b_hi[2 * p][0], b_hi[2 * p][1],
                        b_hi[2 * p + 1][0], b_hi[2 * p + 1][1], addr_h);
            }
            // product 1: a_hi * b_hi
#pragma unroll
            for (int mi = 0; mi < 2; mi++)
#pragma unroll
                for (int nj = 0; nj < 8; nj++)
                    MMA16816(acc[mi][nj], a_hi[mi], b_hi[nj]);

            // product 2: a_lo * b_hi
#pragma unroll
            for (int mi = 0; mi < 2; mi++) {
                int row = aRow + mi * 16;
                uint32_t addr_l = ab + row * 128u +
                                  (uint32_t)(((4 + kk * 2 + aU) ^ aX) << 4);
                LDSM_X4(a_lo[mi][0], a_lo[mi][1], a_lo[mi][2], a_lo[mi][3], addr_l);
            }
#pragma unroll
            for (int mi = 0; mi < 2; mi++)
#pragma unroll
                for (int nj = 0; nj < 8; nj++)
                    MMA16816(acc[mi][nj], a_lo[mi], b_hi[nj]);

            // product 3: a_hi * b_lo
#pragma unroll
            for (int p = 0; p < 4; p++) {
                int row = bRow + p * 16;
                uint32_t addr_l = bb + row * 128u +
                                  (uint32_t)(((4 + kk * 2 + bU) ^ bX) << 4);
                LDSM_X4(b_lo[2 * p][0], b_lo[2 * p][1],
                        b_lo[2 * p + 1][0], b_lo[2 * p + 1][1], addr_l);
            }
#pragma unroll
            for (int mi = 0; mi < 2; mi++)
#pragma unroll
                for (int nj = 0; nj < 8; nj++)
                    MMA16816(acc[mi][nj], a_hi[mi], b_lo[nj]);
        }
        asm volatile("cp.async.wait_group %0;" :: "n"(STAGES - 2));
        __syncthreads();
    }

    // ---- epilogue ----
    const int g = lane >> 2;       // row within m16 half
    const int tig = lane & 3;      // col pair within n8

    if constexpr (PHASE1) {
#pragma unroll
        for (int mi = 0; mi < 2; mi++)
#pragma unroll
            for (int rsel = 0; rsel < 2; rsel++) {
                int grow = blockRow + wm + mi * 16 + g + rsel * 8;
#pragma unroll
                for (int nj = 0; nj < 8; nj++) {
                    int cc = colbase + wn + nj * 8 + 2 * tig;
                    float h0 = fmaxf(acc[mi][nj][rsel * 2 + 0] + bias[cc], 0.0f);
                    float h1 = fmaxf(acc[mi][nj][rsel * 2 + 1] + bias[cc + 1], 0.0f);
                    __half hi0, lo0, hi1, lo1;
                    split_h(h0, hi0, lo0);
                    split_h(h1, hi1, lo1);
                    *reinterpret_cast<__half2*>(&g_hhi[(size_t)grow * 512 + cc]) =
                        __halves2half2(hi0, hi1);
                    *reinterpret_cast<__half2*>(&g_hlo[(size_t)grow * 512 + cc]) =
                        __halves2half2(lo0, lo1);
                }
            }
    } else {
        const float e = eta[0];
        float bb2[8][2];
#pragma unroll
        for (int nj = 0; nj < 8; nj++) {
            int cc = colbase + wn + nj * 8 + 2 * tig;
            bb2[nj][0] = bias[cc] * e;
            bb2[nj][1] = bias[cc + 1] * e;
        }
        const int dbase = (colbase + wn) >> 4;

#pragma unroll
        for (int mi = 0; mi < 2; mi++)
#pragma unroll
            for (int rsel = 0; rsel < 2; rsel++) {
                int grow = blockRow + wm + mi * 16 + g + rsel * 8;
#pragma unroll
                for (int dj = 0; dj < 4; dj++) {
                    int d = dbase + dj;
                    float th = theta[grow * DH + d];
                    float rr = r_in[grow * DH + d];
                    float sn, cs;
                    sincosf(th, &sn, &cs);
                    float z0 = rr * cs, z1 = rr * sn;
                    float rr2 = rr * rr;
                    float sumT = 0.0f, sumS = 0.0f;
#pragma unroll
                    for (int hf = 0; hf < 2; hf++) {
                        int nj = 2 * dj + hf;
                        float p0 = acc[mi][nj][rsel * 2 + 0] + bb2[nj][0];
                        float p1 = acc[mi][nj][rsel * 2 + 1] + bb2[nj][1];
                        float nrm = sqrtf(p0 * p0 + p1 * p1);
                        float f = rr * 0.99f / (1.0f + nrm);
                        float w0 = f * p0, w1 = f * p1;
                        float zw0 = z0 - w0, zw1 = z1 - w1;
                        float dist2 = zw0 * zw0 + zw1 * zw1;
                        float scale = (rr2 - (w0 * w0 + w1 * w1)) / dist2;
                        float zo0 = scale * zw0 - w0;
                        float zo1 = scale * zw1 - w1;
                        float ang = atan2f(zo1, zo0);
                        if (ang < 0.0f) ang += TWO_PI_F;
                        sumT += ang;
                        sumS += scale;
                    }
                    sumT += __shfl_xor_sync(0xffffffffu, sumT, 1);
                    sumS += __shfl_xor_sync(0xffffffffu, sumS, 1);
                    sumT += __shfl_xor_sync(0xffffffffu, sumT, 2);
                    sumS += __shfl_xor_sync(0xffffffffu, sumS, 2);
                    if (tig == 0) {
                        out[grow * DH + d] = sumT * 0.125f;
                        out[(size_t)B_TOTAL * DH + grow * DH + d] =
                            logf(sumS * 0.125f + 1e-8f);
                    }
                }
            }
    }
#undef LDSM_X4
#undef MMA16816
}

// ---------------- launch ----------------
extern "C" void kernel_launch(void* const* d_in, const int* in_sizes, int n_in,
                              void* d_out, int out_size) {
    const float* theta = (const float*)d_in[0];
    const float* r     = (const float*)d_in[1];
    const float* x     = (const float*)d_in[2];
    const float* W1    = (const float*)d_in[3];
    const float* b1    = (const float*)d_in[4];
    const float* W2    = (const float*)d_in[5];
    const float* b2    = (const float*)d_in[6];
    const float* eta   = (const float*)d_in[7];
    float* out = (float*)d_out;

    pack_x_kernel<<<(B_TOTAL * 64) / 256, 256>>>(x);
    pack_w1_kernel<<<(512 * 64) / 256, 256>>>(W1);
    pack_w2_kernel<<<(512 * 512) / 256, 256>>>(W2, eta);

    const int smem_bytes = 3 * 32768;   // 96 KB, 3-stage pipeline, 2 CTAs/SM
    cudaFuncSetAttribute(mma_gemm_kernel<64, true>,
                         cudaFuncAttributeMaxDynamicSharedMemorySize, smem_bytes);
    cudaFuncSetAttribute(mma_gemm_kernel<512, false>,
                         cudaFuncAttributeMaxDynamicSharedMemorySize, smem_bytes);

    dim3 grid(4, B_TOTAL / 128);   // n-quarter fast => row-sharing CTAs adjacent
    mma_gemm_kernel<64, true><<<grid, 256, smem_bytes>>>(
        b1, nullptr, nullptr, nullptr, nullptr);
    mma_gemm_kernel<512, false><<<grid, 256, smem_bytes>>>(
        b2, theta, r, eta, out);
}

// round 11
// speedup vs baseline: 1.0449x; 1.0449x over previous
#include <cuda_runtime.h>
#include <cuda_fp16.h>
#include <math.h>
#include <stdint.h>

// ---------------- problem constants ----------------
#define B_TOTAL   131072
#define DH        32
#define TWO_PI_F  6.283185307179586f

// ---------------- device scratch (static, no alloc) ----------------
__device__ __half g_xhi[(size_t)B_TOTAL * 64];
__device__ __half g_xlo[(size_t)B_TOTAL * 64];
__device__ __half g_hhi[(size_t)B_TOTAL * 512];
__device__ __half g_hlo[(size_t)B_TOTAL * 512];
__device__ __half g_w1hi[512 * 64];    // W1^T [n=512][k=64]
__device__ __half g_w1lo[512 * 64];
__device__ __half g_w2hi[512 * 512];   // (W2*eta)^T [n=512][k=512]
__device__ __half g_w2lo[512 * 512];

__device__ __forceinline__ void split_h(float v, __half& hi, __half& lo) {
    hi = __float2half_rn(v);
    lo = __float2half_rn(v - __half2float(hi));
}

// ---------------- pack kernels ----------------
__global__ void pack_x_kernel(const float* __restrict__ x) {
    size_t i = (size_t)blockIdx.x * blockDim.x + threadIdx.x;  // B*64
    __half hi, lo;
    split_h(x[i], hi, lo);
    g_xhi[i] = hi;
    g_xlo[i] = lo;
}
__global__ void pack_w1_kernel(const float* __restrict__ W1) {
    int i = blockIdx.x * blockDim.x + threadIdx.x;   // 512*64
    int n = i >> 6, k = i & 63;
    __half hi, lo;
    split_h(W1[k * 512 + n], hi, lo);
    g_w1hi[i] = hi;    // [n][k] layout, i = n*64+k
    g_w1lo[i] = lo;
}
__global__ void pack_w2_kernel(const float* __restrict__ W2,
                               const float* __restrict__ eta) {
    int i = blockIdx.x * blockDim.x + threadIdx.x;   // 512*512
    int n = i >> 9, k = i & 511;
    __half hi, lo;
    split_h(W2[k * 513 + n] * eta[0], hi, lo);
    g_w2hi[i] = hi;    // [n][k], i = n*512+k
    g_w2lo[i] = lo;
}

// ---------------------------------------------------------------------------
// fp16x3-split GEMM via mma.sync m16n8k16, fused hi/lo chunks.
// CTA: 256 threads (8 warps), 2 CTAs/SM. Tile M=128 x N=128;
// warp grid 4(m) x 2(n), warp tile 32x64 -> acc[2][8][4] fp32.
// Chunk = k32 slice: smem rows are 128B = [hi 64B | lo 64B] for both A and B.
// Per k16 step: LDSM a_hi,b_hi,a_lo -> P1 (a_hi*b_hi) -> LDSM b_lo ->
// P2 (a_lo*b_hi) -> P3 (a_hi*b_lo): every LDS latency hides under >=16 MMAs.
// 3-stage cp.async pipeline (96KB/CTA), 16B-XOR swizzle.
// Epilogues stage output tiles in smem -> fully coalesced global stores
// (raw fragment stores had 4-8x sector write-amplification).
// PHASE1: A=x splits, B=W1^T splits, epilogue relu+split -> g_h{hi,lo}
// PHASE2: A=h splits, B=(W2*eta)^T splits, epilogue Moebius -> out
// ---------------------------------------------------------------------------
template <int KSEG, bool PHASE1>
__global__ __launch_bounds__(256, 2)
void mma_gemm_kernel(const float* __restrict__ bias,
                     const float* __restrict__ theta,
                     const float* __restrict__ r_in,
                     const float* __restrict__ eta,
                     float* __restrict__ out) {
    constexpr int NC = KSEG / 32;       // k32 chunks
    constexpr int SSTRIDE = KSEG * 2;   // source row stride (bytes)
    constexpr int STAGES = 3;
    constexpr int CHUNK_BYTES = 32768;  // A 16KB + B 16KB

    extern __shared__ char smem[];
    const uint32_t sbase = (uint32_t)__cvta_generic_to_shared(smem);

    const int tid = threadIdx.x;
    const int lane = tid & 31;
    const int wid = tid >> 5;
    const int wm = (wid & 3) * 32;       // warp M offset within CTA tile
    const int wn = (wid >> 2) * 64;      // warp N offset within CTA tile
    const int blockRow = blockIdx.y * 128;
    const int colbase = blockIdx.x * 128;

    const __half* Ahi = PHASE1 ? g_xhi : g_hhi;
    const __half* Alo = PHASE1 ? g_xlo : g_hlo;
    const __half* Bhi = PHASE1 ? g_w1hi : g_w2hi;
    const __half* Blo = PHASE1 ? g_w1lo : g_w2lo;

    float acc[2][8][4];
#pragma unroll
    for (int mi = 0; mi < 2; mi++)
#pragma unroll
        for (int nj = 0; nj < 8; nj++)
#pragma unroll
            for (int q = 0; q < 4; q++) acc[mi][nj][q] = 0.0f;

    // ldmatrix lane-address components.
    const int aRow = wm + (lane & 7) + ((lane >> 3) & 1) * 8;
    const int aU = (lane >> 4) & 1;
    const int aX = aRow & 7;
    const int bRow = wn + (lane & 7) + ((lane >> 4) & 1) * 8;
    const int bU = (lane >> 3) & 1;
    const int bX = bRow & 7;

    // chunk kc covers k-columns [kc*32, kc*32+32); smem row = [hi 64B | lo 64B]
    auto loadc = [&](int kc) {
        const char* ah = (const char*)Ahi + (size_t)blockRow * SSTRIDE + (size_t)kc * 64;
        const char* al = (const char*)Alo + (size_t)blockRow * SSTRIDE + (size_t)kc * 64;
        const char* bh = (const char*)Bhi + (size_t)colbase * SSTRIDE + (size_t)kc * 64;
        const char* bl = (const char*)Blo + (size_t)colbase * SSTRIDE + (size_t)kc * 64;
        uint32_t ab = sbase + (uint32_t)(kc % STAGES) * CHUNK_BYTES;
        uint32_t bb = ab + 16384u;
#pragma unroll
        for (int j = 0; j < 4; j++) {                 // A: 1024 x 16B units
            int gi = tid + 256 * j;
            int row = gi >> 3, u = gi & 7;
            const char* base = (u < 4) ? ah : al;
            const char* src = base + (size_t)row * SSTRIDE + (u & 3) * 16;
            uint32_t dst = ab + row * 128u + (uint32_t)((u ^ (row & 7)) << 4);
            asm volatile("cp.async.cg.shared.global [%0], [%1], 16;"
                         :: "r"(dst), "l"(src));
        }
#pragma unroll
        for (int j = 0; j < 4; j++) {                 // B: 1024 x 16B units
            int gi = tid + 256 * j;
            int row = gi >> 3, u = gi & 7;
            const char* base = (u < 4) ? bh : bl;
            const char* src = base + (size_t)row * SSTRIDE + (u & 3) * 16;
            uint32_t dst = bb + row * 128u + (uint32_t)((u ^ (row & 7)) << 4);
            asm volatile("cp.async.cg.shared.global [%0], [%1], 16;"
                         :: "r"(dst), "l"(src));
        }
        asm volatile("cp.async.commit_group;");
    };

#define LDSM_X4(r0, r1, r2, r3, addr)                                        \
    asm volatile(                                                            \
        "ldmatrix.sync.aligned.m8n8.x4.shared.b16 {%0,%1,%2,%3}, [%4];"      \
        : "=r"(r0), "=r"(r1), "=r"(r2), "=r"(r3) : "r"(addr))

#define MMA16816(d, a, b)                                                    \
    asm volatile(                                                            \
        "mma.sync.aligned.m16n8k16.row.col.f32.f16.f16.f32 "                 \
        "{%0,%1,%2,%3}, {%4,%5,%6,%7}, {%8,%9}, {%0,%1,%2,%3};"              \
        : "+f"((d)[0]), "+f"((d)[1]), "+f"((d)[2]), "+f"((d)[3])             \
        : "r"((a)[0]), "r"((a)[1]), "r"((a)[2]), "r"((a)[3]),                \
          "r"((b)[0]), "r"((b)[1]))

    // ---- prologue: fill STAGES-1 buffers ----
#pragma unroll
    for (int s = 0; s < STAGES - 1; s++) {
        if (s < NC) loadc(s);
        else asm volatile("cp.async.commit_group;");
    }
    asm volatile("cp.async.wait_group %0;" :: "n"(STAGES - 2));
    __syncthreads();   // chunk 0 visible

#pragma unroll 1
    for (int c = 0; c < NC; c++) {
        if (c + STAGES - 1 < NC) loadc(c + STAGES - 1);
        else asm volatile("cp.async.commit_group;");

        uint32_t ab = sbase + (uint32_t)(c % STAGES) * CHUNK_BYTES;
        uint32_t bb = ab + 16384u;
#pragma unroll
        for (int kk = 0; kk < 2; kk++) {
            // hi units 0..3 hold k slice, lo units 4..7 hold the lo split
            uint32_t a_hi[2][4], a_lo[2][4];
            uint32_t b_hi[8][2], b_lo[8][2];
            // hoisted loads: a_hi, b_hi, a_lo (P2's a_lo hides under P1)
#pragma unroll
            for (int mi = 0; mi < 2; mi++) {
                int row = aRow + mi * 16;
                uint32_t addr_h = ab + row * 128u +
                                  (uint32_t)(((kk * 2 + aU) ^ aX) << 4);
                LDSM_X4(a_hi[mi][0], a_hi[mi][1], a_hi[mi][2], a_hi[mi][3], addr_h);
            }
#pragma unroll
            for (int p = 0; p < 4; p++) {
                int row = bRow + p * 16;
                uint32_t addr_h = bb + row * 128u +
                                  (uint32_t)(((kk * 2 + bU) ^ bX) << 4);
                LDSM_X4(b_hi[2 * p][0], b_hi[2 * p][1],
                        b_hi[2 * p + 1][0], b_hi[2 * p + 1][1], addr_h);
            }
#pragma unroll
            for (int mi = 0; mi < 2; mi++) {
                int row = aRow + mi * 16;
                uint32_t addr_l = ab + row * 128u +
                                  (uint32_t)(((4 + kk * 2 + aU) ^ aX) << 4);
                LDSM_X4(a_lo[mi][0], a_lo[mi][1], a_lo[mi][2], a_lo[mi][3], addr_l);
            }
            // product 1: a_hi * b_hi
#pragma unroll
            for (int mi = 0; mi < 2; mi++)
#pragma unroll
                for (int nj = 0; nj < 8; nj++)
                    MMA16816(acc[mi][nj], a_hi[mi], b_hi[nj]);
            // load b_lo (P3's operand hides under P2)
#pragma unroll
            for (int p = 0; p < 4; p++) {
                int row = bRow + p * 16;
                uint32_t addr_l = bb + row * 128u +
                                  (uint32_t)(((4 + kk * 2 + bU) ^ bX) << 4);
                LDSM_X4(b_lo[2 * p][0], b_lo[2 * p][1],
                        b_lo[2 * p + 1][0], b_lo[2 * p + 1][1], addr_l);
            }
            // product 2: a_lo * b_hi
#pragma unroll
            for (int mi = 0; mi < 2; mi++)
#pragma unroll
                for (int nj = 0; nj < 8; nj++)
                    MMA16816(acc[mi][nj], a_lo[mi], b_hi[nj]);
            // product 3: a_hi * b_lo
#pragma unroll
            for (int mi = 0; mi < 2; mi++)
#pragma unroll
                for (int nj = 0; nj < 8; nj++)
                    MMA16816(acc[mi][nj], a_hi[mi], b_lo[nj]);
        }
        asm volatile("cp.async.wait_group %0;" :: "n"(STAGES - 2));
        __syncthreads();
    }

    // ---- epilogue ----
    const int g = lane >> 2;       // row within m16 half
    const int tig = lane & 3;      // col pair within n8

    if constexpr (PHASE1) {
        // stage hi/lo tiles in smem (row stride 136 halves; banks 4g+tig
        // conflict-free), then coalesced uint4 stores to global.
        __half* s_hi = reinterpret_cast<__half*>(smem);             // 128x136
        __half* s_lo = reinterpret_cast<__half*>(smem + 128 * 272); // 128x136
#pragma unroll
        for (int mi = 0; mi < 2; mi++)
#pragma unroll
            for (int rsel = 0; rsel < 2; rsel++) {
                int rloc = wm + mi * 16 + g + rsel * 8;
#pragma unroll
                for (int nj = 0; nj < 8; nj++) {
                    int cloc = wn + nj * 8 + 2 * tig;
                    int cc = colbase + cloc;
                    float h0 = fmaxf(acc[mi][nj][rsel * 2 + 0] + bias[cc], 0.0f);
                    float h1 = fmaxf(acc[mi][nj][rsel * 2 + 1] + bias[cc + 1], 0.0f);
                    __half hi0, lo0, hi1, lo1;
                    split_h(h0, hi0, lo0);
                    split_h(h1, hi1, lo1);
                    *reinterpret_cast<__half2*>(&s_hi[rloc * 136 + cloc]) =
                        __halves2half2(hi0, hi1);
                    *reinterpret_cast<__half2*>(&s_lo[rloc * 136 + cloc]) =
                        __halves2half2(lo0, lo1);
                }
            }
        __syncthreads();
#pragma unroll
        for (int it = 0; it < 8; it++) {
            int idx = tid + it * 256;           // 2048 = 128 rows x 16 segs
            int row = idx >> 4, seg = idx & 15;
            uint4 v = *reinterpret_cast<uint4*>(&s_hi[row * 136 + seg * 8]);
            *reinterpret_cast<uint4*>(
                &g_hhi[(size_t)(blockRow + row) * 512 + colbase + seg * 8]) = v;
            uint4 w = *reinterpret_cast<uint4*>(&s_lo[row * 136 + seg * 8]);
            *reinterpret_cast<uint4*>(
                &g_hlo[(size_t)(blockRow + row) * 512 + colbase + seg * 8]) = w;
        }
    } else {
        const float e = eta[0];
        float bb2[8][2];
#pragma unroll
        for (int nj = 0; nj < 8; nj++) {
            int cc = colbase + wn + nj * 8 + 2 * tig;
            bb2[nj][0] = bias[cc] * e;
            bb2[nj][1] = bias[cc + 1] * e;
        }
        const int dbase = (colbase + wn) >> 4;
        const int d0c = colbase >> 4;
        // staging: s_out[row][tensor*8 + dlocal], row stride 17 floats (pad)
        float* s_out = reinterpret_cast<float*>(smem);

#pragma unroll
        for (int mi = 0; mi < 2; mi++)
#pragma unroll
            for (int rsel = 0; rsel < 2; rsel++) {
                int rloc = wm + mi * 16 + g + rsel * 8;
                int grow = blockRow + rloc;
#pragma unroll
                for (int dj = 0; dj < 4; dj++) {
                    int d = dbase + dj;
                    float th = theta[grow * DH + d];
                    float rr = r_in[grow * DH + d];
                    float sn, cs;
                    sincosf(th, &sn, &cs);
                    float z0 = rr * cs, z1 = rr * sn;
                    float rr2 = rr * rr;
                    float sumT = 0.0f, sumS = 0.0f;
#pragma unroll
                    for (int hf = 0; hf < 2; hf++) {
                        int nj = 2 * dj + hf;
                        float p0 = acc[mi][nj][rsel * 2 + 0] + bb2[nj][0];
                        float p1 = acc[mi][nj][rsel * 2 + 1] + bb2[nj][1];
                        float nrm = sqrtf(p0 * p0 + p1 * p1);
                        float f = rr * 0.99f / (1.0f + nrm);
                        float w0 = f * p0, w1 = f * p1;
                        float zw0 = z0 - w0, zw1 = z1 - w1;
                        float dist2 = zw0 * zw0 + zw1 * zw1;
                        float scale = (rr2 - (w0 * w0 + w1 * w1)) / dist2;
                        float zo0 = scale * zw0 - w0;
                        float zo1 = scale * zw1 - w1;
                        float ang = atan2f(zo1, zo0);
                        if (ang < 0.0f) ang += TWO_PI_F;
                        sumT += ang;
                        sumS += scale;
                    }
                    sumT += __shfl_xor_sync(0xffffffffu, sumT, 1);
                    sumS += __shfl_xor_sync(0xffffffffu, sumS, 1);
                    sumT += __shfl_xor_sync(0xffffffffu, sumT, 2);
                    sumS += __shfl_xor_sync(0xffffffffu, sumS, 2);
                    if (tig == 0) {
                        int dl = d - d0c;   // 0..7 within CTA
                        s_out[rloc * 17 + dl] = sumT * 0.125f;
                        s_out[rloc * 17 + 8 + dl] = logf(sumS * 0.125f + 1e-8f);
                    }
                }
            }
        __syncthreads();
#pragma unroll
        for (int it = 0; it < 8; it++) {
            int idx = tid + it * 256;        // 2048 = 128 rows x 2 tensors x 8 d
            int row = idx >> 4;
            int rest = idx & 15;
            int t = rest >> 3;
            int dl = rest & 7;
            float v = s_out[row * 17 + t * 8 + dl];
            out[(size_t)t * B_TOTAL * DH + (size_t)(blockRow + row) * DH +
                d0c + dl] = v;
        }
    }
#undef LDSM_X4
#undef MMA16816
}

// ---------------- launch ----------------
extern "C" void kernel_launch(void* const* d_in, const int* in_sizes, int n_in,
                              void* d_out, int out_size) {
    const float* theta = (const float*)d_in[0];
    const float* r     = (const float*)d_in[1];
    const float* x     = (const float*)d_in[2];
    const float* W1    = (const float*)d_in[3];
    const float* b1    = (const float*)d_in[4];
    const float* W2    = (const float*)d_in[5];
    const float* b2    = (const float*)d_in[6];
    const float* eta   = (const float*)d_in[7];
    float* out = (float*)d_out;

    pack_x_kernel<<<(B_TOTAL * 64) / 256, 256>>>(x);
    pack_w1_kernel<<<(512 * 64) / 256, 256>>>(W1);
    pack_w2_kernel<<<(512 * 512) / 256, 256>>>(W2, eta);

    const int smem_bytes = 3 * 32768;   // 96 KB, 3-stage pipeline, 2 CTAs/SM
    cudaFuncSetAttribute(mma_gemm_kernel<64, true>,
                         cudaFuncAttributeMaxDynamicSharedMemorySize, smem_bytes);
    cudaFuncSetAttribute(mma_gemm_kernel<512, false>,
                         cudaFuncAttributeMaxDynamicSharedMemorySize, smem_bytes);

    dim3 grid(4, B_TOTAL / 128);   // n-quarter fast => row-sharing CTAs adjacent
    mma_gemm_kernel<64, true><<<grid, 256, smem_bytes>>>(
        b1, nullptr, nullptr, nullptr, nullptr);
    mma_gemm_kernel<512, false><<<grid, 256, smem_bytes>>>(
        b2, theta, r, eta, out);
}